// round 14
// baseline (speedup 1.0000x reference)
#include <cuda_runtime.h>
#include <cuda_fp16.h>
#include <cstdint>
#include <math.h>

#define SDIM 2048
#define HDIM 2048
#define ANUM 16
#define NB_A 256      // K1 type-A blocks (layer0 gates, 8 units each)
#define NB_B 256      // K1 type-B blocks (layer1 recurrent, 32 rows each)
#define NB_3 256      // K3 blocks (8 logit rows each, half-row per warp)
#define NLOGBLK 128   // step-0 logits_cvt grid
#define R_A  4        // unit-groups per cvt block
#define CH   8        // chunks per row (2048 / 256)
#define CC   256      // halfs per chunk per row per matrix
#define NSTG 3        // pipeline stages (K1/K2)

// Persistent scratch
__device__ __align__(16) float g_h0[2][HDIM];
__device__ __align__(16) float g_h1[2][HDIM];
__device__ __align__(16) float g_c[2][HDIM];
__device__ __align__(16) float g_pre1[4 * HDIM];
__device__ __align__(16) float g_logits[SDIM];
__device__ __align__(16) float g_partial[NB_3];
__device__ __align__(16) __half g_wih16[2 * 4 * HDIM * HDIM];
__device__ __align__(16) __half g_whh16[2 * 4 * HDIM * HDIM];
__device__ __align__(16) __half g_wout16[SDIM * HDIM];

__device__ __forceinline__ float sigmoidf_(float x) {
    return 1.0f / (1.0f + __expf(-x));
}

__device__ __forceinline__ void cp16(uint32_t dst, const void* src) {
    asm volatile("cp.async.cg.shared.global [%0], [%1], 16;"
                 :: "r"(dst), "l"(src) : "memory");
}
#define CP_COMMIT() asm volatile("cp.async.commit_group;" ::: "memory")
#define CP_WAIT1()  asm volatile("cp.async.wait_group 1;"  ::: "memory")

// 8 half-weights (uint4) dot 8 floats (two float4), into two accumulators.
__device__ __forceinline__ void dot8(uint4 w, float4 lo, float4 hi,
                                     float& p, float& q) {
    const __half2* hp = reinterpret_cast<const __half2*>(&w);
    float2 f0 = __half22float2(hp[0]);
    float2 f1 = __half22float2(hp[1]);
    float2 f2 = __half22float2(hp[2]);
    float2 f3 = __half22float2(hp[3]);
    p = fmaf(f0.x, lo.x, p); q = fmaf(f0.y, lo.y, q);
    p = fmaf(f1.x, lo.z, p); q = fmaf(f1.y, lo.w, q);
    p = fmaf(f2.x, hi.x, p); q = fmaf(f2.y, hi.y, q);
    p = fmaf(f3.x, hi.z, p); q = fmaf(f3.y, hi.w, q);
}

// ===========================================================================
// K1 (steady, R11 verbatim): type-A = layer-0 full gates (+inline softmax);
//                            type-B = layer-1 recurrent partials -> pre1.
// ===========================================================================
template<int FIRST>
__global__ void __launch_bounds__(512, 2) step_k1(
    const __half* __restrict__ Wih0, const __half* __restrict__ Whh0,
    const __half* __restrict__ Whh1,
    const float* __restrict__ bih0, const float* __restrict__ bhh0,
    const float* __restrict__ bih1, const float* __restrict__ bhh1,
    const float* __restrict__ xin,
    const float* __restrict__ logits, const float* __restrict__ partials,
    float* __restrict__ out_prev,
    const float* __restrict__ h0_in, float* __restrict__ h0_out,
    const float* __restrict__ h1_in,
    float* __restrict__ c0, float* __restrict__ pre1)
{
    extern __shared__ __align__(16) char smem[];
    float4* sIn0 = (float4*)smem;
    float4* sIn1 = sIn0 + 256;
    float4* sH0  = sIn1 + 256;
    float4* sH1  = sH0 + 256;
    __half* tiles = (__half*)(smem + 16384);
    __shared__ float s_g[32];
    __shared__ float s_inv;

    const int t = threadIdx.x, warp = t >> 5, lane = t & 31;
    const bool typeA = (blockIdx.x < NB_A);
    const uint32_t smemU = (uint32_t)__cvta_generic_to_shared(smem);
    const uint32_t tileU = smemU + 16384 + warp * 6144 + lane * 16;
    const __half* tileh  = tiles + warp * 3072;

    int rg0;
    const __half *rA0, *rB0;
    if (typeA) {
        const int i0 = 2 * warp;
        rg0 = (i0 >> 3) * HDIM + blockIdx.x * 8 + (i0 & 7);
        rA0 = Wih0 + (size_t)rg0 * HDIM;
        rB0 = Whh0 + (size_t)rg0 * HDIM;
    } else {
        rg0 = (blockIdx.x - NB_A) * 32 + 2 * warp;
        rA0 = Whh1 + (size_t)rg0 * HDIM;
        rB0 = nullptr;
    }

    if (typeA) {
        #pragma unroll
        for (int s = 0; s < NSTG - 1; s++) {
            const uint32_t d = tileU + s * 2048;
            cp16(d,        rA0 + s * CC + lane * 8);
            cp16(d + 512,  rA0 + HDIM + s * CC + lane * 8);
            cp16(d + 1024, rB0 + s * CC + lane * 8);
            cp16(d + 1536, rB0 + HDIM + s * CC + lane * 8);
            CP_COMMIT();
        }
    } else {
        #pragma unroll
        for (int s = 0; s < NSTG - 1; s++) {
            const uint32_t d = tileU + s * 2048;
            cp16(d,       rA0 + s * CC + lane * 8);
            cp16(d + 512, rA0 + HDIM + s * CC + lane * 8);
            CP_COMMIT();
        }
    }

    if (typeA) {
        if (!FIRST) {
            if (warp == 0) {
                float s = 0.0f;
                #pragma unroll
                for (int j = 0; j < 8; j++) s += partials[lane + j * 32];
                #pragma unroll
                for (int o = 16; o > 0; o >>= 1)
                    s += __shfl_xor_sync(0xffffffffu, s, o);
                if (lane == 0) s_inv = 1.0f / s;
            }
            __syncthreads();
        }
        float4 v;
        if (FIRST) {
            v = ((const float4*)xin)[t];
        } else {
            float4 lg = ((const float4*)logits)[t];
            const float inv = s_inv;
            v.x = __expf(lg.x) * inv;
            v.y = __expf(lg.y) * inv;
            v.z = __expf(lg.z) * inv;
            v.w = __expf(lg.w) * inv;
            if (blockIdx.x == 0) ((float4*)out_prev)[t] = v;
        }
        ((t & 1) ? sIn1 : sIn0)[t >> 1] = v;
        float4 hv = ((const float4*)h0_in)[t];
        ((t & 1) ? sH1 : sH0)[t >> 1] = hv;
    } else {
        float4 hv = ((const float4*)h1_in)[t];
        ((t & 1) ? sIn1 : sIn0)[t >> 1] = hv;
    }
    __syncthreads();

    float p0 = 0.f, q0 = 0.f, p1 = 0.f, q1 = 0.f;
    if (typeA) {
        #pragma unroll
        for (int c = 0; c < CH; c++) {
            CP_WAIT1();
            const int st = c % NSTG;
            const float4 a0 = sIn0[c * 32 + lane], a1 = sIn1[c * 32 + lane];
            const float4 b0 = sH0[c * 32 + lane],  b1 = sH1[c * 32 + lane];
            const __half* tp = tileh + st * 1024;
            uint4 wA0 = *(const uint4*)(tp +       lane * 8);
            uint4 wA1 = *(const uint4*)(tp + 256 + lane * 8);
            uint4 wB0 = *(const uint4*)(tp + 512 + lane * 8);
            uint4 wB1 = *(const uint4*)(tp + 768 + lane * 8);
            dot8(wA0, a0, a1, p0, q0);
            dot8(wB0, b0, b1, p0, q0);
            dot8(wA1, a0, a1, p1, q1);
            dot8(wB1, b0, b1, p1, q1);
            const int nc = c + NSTG - 1;
            if (nc < CH) {
                const uint32_t d = tileU + (nc % NSTG) * 2048;
                cp16(d,        rA0 + nc * CC + lane * 8);
                cp16(d + 512,  rA0 + HDIM + nc * CC + lane * 8);
                cp16(d + 1024, rB0 + nc * CC + lane * 8);
                cp16(d + 1536, rB0 + HDIM + nc * CC + lane * 8);
            }
            CP_COMMIT();
        }
    } else {
        #pragma unroll
        for (int c = 0; c < CH; c++) {
            CP_WAIT1();
            const int st = c % NSTG;
            const float4 a0 = sIn0[c * 32 + lane], a1 = sIn1[c * 32 + lane];
            const __half* tp = tileh + st * 1024;
            uint4 wA0 = *(const uint4*)(tp +       lane * 8);
            uint4 wA1 = *(const uint4*)(tp + 256 + lane * 8);
            dot8(wA0, a0, a1, p0, q0);
            dot8(wA1, a0, a1, p1, q1);
            const int nc = c + NSTG - 1;
            if (nc < CH) {
                const uint32_t d = tileU + (nc % NSTG) * 2048;
                cp16(d,       rA0 + nc * CC + lane * 8);
                cp16(d + 512, rA0 + HDIM + nc * CC + lane * 8);
            }
            CP_COMMIT();
        }
    }

    float v0 = p0 + q0, v1 = p1 + q1;
    #pragma unroll
    for (int o = 16; o > 0; o >>= 1) {
        v0 += __shfl_xor_sync(0xffffffffu, v0, o);
        v1 += __shfl_xor_sync(0xffffffffu, v1, o);
    }
    if (typeA) {
        if (lane == 0) {
            s_g[2 * warp]     = v0 + bih0[rg0] + bhh0[rg0];
            s_g[2 * warp + 1] = v1 + bih0[rg0 + 1] + bhh0[rg0 + 1];
        }
        __syncthreads();
        if (t < 8) {
            const int u = blockIdx.x * 8 + t;
            float iv = sigmoidf_(s_g[t]);
            float fv = sigmoidf_(s_g[8 + t]);
            float gv = tanhf(s_g[16 + t]);
            float ov = sigmoidf_(s_g[24 + t]);
            float cn = fv * c0[u] + iv * gv;
            c0[u]     = cn;
            h0_out[u] = ov * tanhf(cn);
        }
    } else {
        if (lane == 0) {
            pre1[rg0]     = v0 + bih1[rg0] + bhh1[rg0];
            pre1[rg0 + 1] = v1 + bih1[rg0 + 1] + bhh1[rg0 + 1];
        }
    }
}

// ===========================================================================
// K2 (steady, R11 verbatim): layer-1 input half + pointwise.
// ===========================================================================
__global__ void __launch_bounds__(512, 2) step_k2(
    const __half* __restrict__ Wih1,
    const float* __restrict__ pre1,
    const float* __restrict__ h0_new,
    float* __restrict__ h1_out, float* __restrict__ c1)
{
    extern __shared__ __align__(16) char smem[];
    float4* sA0 = (float4*)smem;
    float4* sA1 = sA0 + 256;
    __half* tiles = (__half*)(smem + 8192);
    __shared__ float s_g[32];

    const int t = threadIdx.x, warp = t >> 5, lane = t & 31;
    const uint32_t smemU = (uint32_t)__cvta_generic_to_shared(smem);
    const uint32_t tileU = smemU + 8192 + warp * 3072 + lane * 16;
    const __half* tileh  = tiles + warp * 1536;

    const int i0 = 2 * warp;
    const int rg0 = (i0 >> 3) * HDIM + blockIdx.x * 8 + (i0 & 7);
    const __half* rA0 = Wih1 + (size_t)rg0 * HDIM;

    #pragma unroll
    for (int s = 0; s < NSTG - 1; s++) {
        const uint32_t d = tileU + s * 1024;
        cp16(d,       rA0 + s * CC + lane * 8);
        cp16(d + 512, rA0 + HDIM + s * CC + lane * 8);
        CP_COMMIT();
    }

    {
        float4 hv = ((const float4*)h0_new)[t];
        ((t & 1) ? sA1 : sA0)[t >> 1] = hv;
    }
    __syncthreads();

    float p0 = 0.f, q0 = 0.f, p1 = 0.f, q1 = 0.f;
    #pragma unroll
    for (int c = 0; c < CH; c++) {
        CP_WAIT1();
        const int st = c % NSTG;
        const float4 a0 = sA0[c * 32 + lane], a1 = sA1[c * 32 + lane];
        const __half* tp = tileh + st * 512;
        uint4 w0 = *(const uint4*)(tp +       lane * 8);
        uint4 w1 = *(const uint4*)(tp + 256 + lane * 8);
        dot8(w0, a0, a1, p0, q0);
        dot8(w1, a0, a1, p1, q1);
        const int nc = c + NSTG - 1;
        if (nc < CH) {
            const uint32_t d = tileU + (nc % NSTG) * 1024;
            cp16(d,       rA0 + nc * CC + lane * 8);
            cp16(d + 512, rA0 + HDIM + nc * CC + lane * 8);
        }
        CP_COMMIT();
    }

    float v0 = p0 + q0, v1 = p1 + q1;
    #pragma unroll
    for (int o = 16; o > 0; o >>= 1) {
        v0 += __shfl_xor_sync(0xffffffffu, v0, o);
        v1 += __shfl_xor_sync(0xffffffffu, v1, o);
    }
    if (lane == 0) {
        s_g[2 * warp]     = v0 + pre1[rg0];
        s_g[2 * warp + 1] = v1 + pre1[rg0 + 1];
    }
    __syncthreads();
    if (t < 8) {
        const int u = blockIdx.x * 8 + t;
        float iv = sigmoidf_(s_g[t]);
        float fv = sigmoidf_(s_g[8 + t]);
        float gv = tanhf(s_g[16 + t]);
        float ov = sigmoidf_(s_g[24 + t]);
        float cn = fv * c1[u] + iv * gv;
        c1[u]     = cn;
        h1_out[u] = ov * tanhf(cn);
    }
}

// ===========================================================================
// K3 (steady, R11 verbatim): logits + per-block exp-sum partials.
// ===========================================================================
__global__ void __launch_bounds__(512, 2) step_k3(
    const __half* __restrict__ Wout,
    const float* __restrict__ bout,
    const float* __restrict__ h,
    float* __restrict__ logits,
    float* __restrict__ partials)
{
    extern __shared__ __align__(16) char smem[];
    float4* sA0 = (float4*)smem;
    float4* sA1 = sA0 + 256;
    __half* tiles = (__half*)(smem + 8192);
    __shared__ float s_part[16];
    __shared__ float s_e[8];

    const int t = threadIdx.x, warp = t >> 5, lane = t & 31;
    const uint32_t tileU = (uint32_t)__cvta_generic_to_shared(smem)
                           + 8192 + warp * 2048 + lane * 16;
    const __half* tileh = tiles + warp * 1024;

    const int row  = blockIdx.x * 8 + (warp >> 1);
    const int half = warp & 1;
    const __half* rA = Wout + (size_t)row * HDIM + half * 1024;

    #pragma unroll
    for (int c = 0; c < 4; c++) {
        cp16(tileU + c * 512, rA + c * CC + lane * 8);
        CP_COMMIT();
    }

    {
        float4 hv = ((const float4*)h)[t];
        ((t & 1) ? sA1 : sA0)[t >> 1] = hv;
    }
    __syncthreads();

    float p = 0.f, q = 0.f;
    const int ab = half * 128;
    asm volatile("cp.async.wait_group 3;" ::: "memory");
    {
        uint4 w = *(const uint4*)(tileh + lane * 8);
        dot8(w, sA0[ab + lane], sA1[ab + lane], p, q);
    }
    asm volatile("cp.async.wait_group 2;" ::: "memory");
    {
        uint4 w = *(const uint4*)(tileh + 256 + lane * 8);
        dot8(w, sA0[ab + 32 + lane], sA1[ab + 32 + lane], p, q);
    }
    asm volatile("cp.async.wait_group 1;" ::: "memory");
    {
        uint4 w = *(const uint4*)(tileh + 512 + lane * 8);
        dot8(w, sA0[ab + 64 + lane], sA1[ab + 64 + lane], p, q);
    }
    asm volatile("cp.async.wait_group 0;" ::: "memory");
    {
        uint4 w = *(const uint4*)(tileh + 768 + lane * 8);
        dot8(w, sA0[ab + 96 + lane], sA1[ab + 96 + lane], p, q);
    }

    float v = p + q;
    #pragma unroll
    for (int o = 16; o > 0; o >>= 1)
        v += __shfl_xor_sync(0xffffffffu, v, o);
    if (lane == 0) s_part[warp] = v;
    __syncthreads();
    if ((warp & 1) == 0 && lane == 0) {
        float lg = s_part[warp] + s_part[warp + 1] + bout[row];
        logits[row] = lg;
        s_e[warp >> 1] = __expf(lg);
    }
    __syncthreads();
    if (t == 0) {
        float se = 0.f;
        #pragma unroll
        for (int j = 0; j < 8; j++) se += s_e[j];
        partials[blockIdx.x] = se;
    }
}

// ===========================================================================
// Step-0 fused (R5-proven): fp32 compute + fp16 cache write, LDG-based.
// Grid 128 x 512, R_A=4 (16 units/block).
// ===========================================================================
__global__ void __launch_bounds__(512) lstm_gates_cvt(
    const float* __restrict__ Wih32, const float* __restrict__ Whh32,
    __half* __restrict__ WihC, __half* __restrict__ WhhC,
    const float* __restrict__ bih, const float* __restrict__ bhh,
    const float* __restrict__ inp,
    const float* __restrict__ hin,
    float* __restrict__ hout,
    float* __restrict__ cio)
{
    __shared__ float4 s_in0[256], s_in1[256], s_h0[256], s_h1[256];
    __shared__ float s_g[4][4];

    const int t    = threadIdx.x;
    const int warp = t >> 5;
    const int lane = t & 31;

    {
        float4 v = ((const float4*)inp)[t];
        ((t & 1) ? s_in1 : s_in0)[t >> 1] = v;
        float4 hv = ((const float4*)hin)[t];
        ((t & 1) ? s_h1 : s_h0)[t >> 1] = hv;
    }
    __syncthreads();

    const int ulocal = warp >> 2;
    const int gate   = warp & 3;
    const float4* sel_in = (lane & 1) ? s_in1 : s_in0;
    const float4* sel_h  = (lane & 1) ? s_h1  : s_h0;

    for (int i = 0; i < R_A; i++) {
        const int unit = blockIdx.x * (4 * R_A) + i * 4 + ulocal;
        const int row  = gate * HDIM + unit;

        const float4* __restrict__ wi32 = (const float4*)Wih32 + (size_t)row * (HDIM / 4);
        const float4* __restrict__ wh32 = (const float4*)Whh32 + (size_t)row * (HDIM / 4);
        uint2* __restrict__ wiC = (uint2*)(WihC + (size_t)row * HDIM);
        uint2* __restrict__ whC = (uint2*)(WhhC + (size_t)row * HDIM);

        float acc0 = 0.f, acc1 = 0.f, acc2 = 0.f, acc3 = 0.f;
        #pragma unroll
        for (int j = 0; j < 16; j += 4) {
            float4 wv[4];
            #pragma unroll
            for (int jj = 0; jj < 4; jj++) wv[jj] = wi32[lane + (j + jj) * 32];
            #pragma unroll
            for (int jj = 0; jj < 4; jj++) {
                const int f = lane + (j + jj) * 32;
                __half2 p0 = __floats2half2_rn(wv[jj].x, wv[jj].y);
                __half2 p1 = __floats2half2_rn(wv[jj].z, wv[jj].w);
                uint2 st; st.x = *(unsigned*)&p0; st.y = *(unsigned*)&p1;
                wiC[f] = st;
                float4 a = sel_in[f >> 1];
                acc0 = fmaf(wv[jj].x, a.x, acc0); acc1 = fmaf(wv[jj].y, a.y, acc1);
                acc2 = fmaf(wv[jj].z, a.z, acc2); acc3 = fmaf(wv[jj].w, a.w, acc3);
            }
        }
        #pragma unroll
        for (int j = 0; j < 16; j += 4) {
            float4 wv[4];
            #pragma unroll
            for (int jj = 0; jj < 4; jj++) wv[jj] = wh32[lane + (j + jj) * 32];
            #pragma unroll
            for (int jj = 0; jj < 4; jj++) {
                const int f = lane + (j + jj) * 32;
                __half2 p0 = __floats2half2_rn(wv[jj].x, wv[jj].y);
                __half2 p1 = __floats2half2_rn(wv[jj].z, wv[jj].w);
                uint2 st; st.x = *(unsigned*)&p0; st.y = *(unsigned*)&p1;
                whC[f] = st;
                float4 a = sel_h[f >> 1];
                acc0 = fmaf(wv[jj].x, a.x, acc0); acc1 = fmaf(wv[jj].y, a.y, acc1);
                acc2 = fmaf(wv[jj].z, a.z, acc2); acc3 = fmaf(wv[jj].w, a.w, acc3);
            }
        }

        float acc = (acc0 + acc1) + (acc2 + acc3);
        #pragma unroll
        for (int o = 16; o > 0; o >>= 1)
            acc += __shfl_xor_sync(0xffffffffu, acc, o);
        if (lane == 0)
            s_g[ulocal][gate] = acc + bih[row] + bhh[row];
        __syncthreads();
        if (t < 4) {
            const int u = blockIdx.x * (4 * R_A) + i * 4 + t;
            float iv = sigmoidf_(s_g[t][0]);
            float fv = sigmoidf_(s_g[t][1]);
            float gv = tanhf(s_g[t][2]);
            float ov = sigmoidf_(s_g[t][3]);
            float cn = fv * cio[u] + iv * gv;
            cio[u]  = cn;
            hout[u] = ov * tanhf(cn);
        }
        __syncthreads();
    }
}

// Step-0 logits (R5-proven): fp32 weights + fp16 cache write. 128 x 512.
// Writes partials[0..NLOGBLK); entries [NLOGBLK, NB_3) must be pre-zeroed.
__global__ void __launch_bounds__(512) logits_cvt(
    const float* __restrict__ Wout32,
    __half* __restrict__ WoutC,
    const float* __restrict__ bout,
    const float* __restrict__ h,
    float* __restrict__ logits,
    float* __restrict__ partials)
{
    __shared__ float4 s_h0[256], s_h1[256];
    __shared__ float s_e[16];

    const int t    = threadIdx.x;
    const int warp = t >> 5;
    const int lane = t & 31;

    {
        float4 hv = ((const float4*)h)[t];
        ((t & 1) ? s_h1 : s_h0)[t >> 1] = hv;
    }
    __syncthreads();

    const int row = blockIdx.x * 16 + warp;
    const float4* __restrict__ w32 = (const float4*)Wout32 + (size_t)row * (HDIM / 4);
    uint2* __restrict__ wC = (uint2*)(WoutC + (size_t)row * HDIM);
    const float4* sel_h = (lane & 1) ? s_h1 : s_h0;

    float acc0 = 0.f, acc1 = 0.f, acc2 = 0.f, acc3 = 0.f;
    #pragma unroll
    for (int j = 0; j < 16; j += 4) {
        float4 wv[4];
        #pragma unroll
        for (int jj = 0; jj < 4; jj++) wv[jj] = w32[lane + (j + jj) * 32];
        #pragma unroll
        for (int jj = 0; jj < 4; jj++) {
            const int f = lane + (j + jj) * 32;
            __half2 p0 = __floats2half2_rn(wv[jj].x, wv[jj].y);
            __half2 p1 = __floats2half2_rn(wv[jj].z, wv[jj].w);
            uint2 st; st.x = *(unsigned*)&p0; st.y = *(unsigned*)&p1;
            wC[f] = st;
            float4 a = sel_h[f >> 1];
            acc0 = fmaf(wv[jj].x, a.x, acc0); acc1 = fmaf(wv[jj].y, a.y, acc1);
            acc2 = fmaf(wv[jj].z, a.z, acc2); acc3 = fmaf(wv[jj].w, a.w, acc3);
        }
    }

    float acc = (acc0 + acc1) + (acc2 + acc3);
    #pragma unroll
    for (int o = 16; o > 0; o >>= 1)
        acc += __shfl_xor_sync(0xffffffffu, acc, o);
    if (lane == 0) {
        float lg = acc + bout[row];
        logits[row] = lg;
        s_e[warp] = __expf(lg);
    }
    __syncthreads();
    if (warp == 0) {
        float v = (lane < 16) ? s_e[lane] : 0.0f;
        #pragma unroll
        for (int o = 16; o > 0; o >>= 1)
            v += __shfl_xor_sync(0xffffffffu, v, o);
        if (lane == 0) partials[blockIdx.x] = v;
    }
}

// Final step's softmax output row.
__global__ void __launch_bounds__(512) final_softmax_kernel(
    const float* __restrict__ logits,
    const float* __restrict__ partials,
    float* __restrict__ out_row)
{
    __shared__ float s_inv;
    const int t = threadIdx.x, warp = t >> 5, lane = t & 31;
    if (warp == 0) {
        float s = 0.0f;
        #pragma unroll
        for (int j = 0; j < 8; j++) s += partials[lane + j * 32];
        #pragma unroll
        for (int o = 16; o > 0; o >>= 1)
            s += __shfl_xor_sync(0xffffffffu, s, o);
        if (lane == 0) s_inv = 1.0f / s;
    }
    __syncthreads();
    const float inv = s_inv;
    float4 lg = ((const float4*)logits)[t];
    float4 v;
    v.x = __expf(lg.x) * inv;
    v.y = __expf(lg.y) * inv;
    v.z = __expf(lg.z) * inv;
    v.w = __expf(lg.w) * inv;
    ((float4*)out_row)[t] = v;
}

// ---------------------------------------------------------------------------
extern "C" void kernel_launch(void* const* d_in, const int* in_sizes, int n_in,
                              void* d_out, int out_size)
{
    const float* x    = (const float*)d_in[0];
    const float* Wih  = (const float*)d_in[1];
    const float* Whh  = (const float*)d_in[2];
    const float* bih  = (const float*)d_in[3];
    const float* bhh  = (const float*)d_in[4];
    const float* Wout = (const float*)d_in[5];
    const float* bout = (const float*)d_in[6];
    float* out = (float*)d_out;

    float *h0, *h1, *cbuf, *gl, *gp, *pre1;
    __half *wih16, *whh16, *wout16;
    cudaGetSymbolAddress((void**)&h0,     g_h0);
    cudaGetSymbolAddress((void**)&h1,     g_h1);
    cudaGetSymbolAddress((void**)&cbuf,   g_c);
    cudaGetSymbolAddress((void**)&gl,     g_logits);
    cudaGetSymbolAddress((void**)&gp,     g_partial);
    cudaGetSymbolAddress((void**)&pre1,   g_pre1);
    cudaGetSymbolAddress((void**)&wih16,  g_wih16);
    cudaGetSymbolAddress((void**)&whh16,  g_whh16);
    cudaGetSymbolAddress((void**)&wout16, g_wout16);

    const int SM_K1 = 16384 + 16 * 6144;   // 114688
    const int SM_K2 = 8192 + 16 * 3072;    // 57344
    const int SM_K3 = 8192 + 16 * 2048;    // 40960
    cudaFuncSetAttribute(step_k1<0>, cudaFuncAttributeMaxDynamicSharedMemorySize, SM_K1);
    cudaFuncSetAttribute(step_k2,    cudaFuncAttributeMaxDynamicSharedMemorySize, SM_K2);
    cudaFuncSetAttribute(step_k3,    cudaFuncAttributeMaxDynamicSharedMemorySize, SM_K3);

    cudaMemsetAsync(h0, 0, sizeof(float) * HDIM);           // h0[0]
    cudaMemsetAsync(h1, 0, sizeof(float) * HDIM);           // h1[0]
    cudaMemsetAsync(cbuf, 0, sizeof(float) * 2 * HDIM);     // c0, c1
    cudaMemsetAsync(gp, 0, sizeof(float) * NB_3);           // partials (step0 fills 128)

    const size_t wOffL = (size_t)4 * HDIM * HDIM;
    const size_t bOffL = (size_t)4 * HDIM;

    // ---- step 0: fused fp32 compute + fp16 cache write (R5-proven) ----
    lstm_gates_cvt<<<128, 512>>>(
        Wih, Whh, wih16, whh16, bih, bhh,
        x, h0 /*zeros*/, h0 + HDIM, cbuf);
    lstm_gates_cvt<<<128, 512>>>(
        Wih + wOffL, Whh + wOffL, wih16 + wOffL, whh16 + wOffL,
        bih + bOffL, bhh + bOffL,
        h0 + HDIM, h1 /*zeros*/, h1 + HDIM, cbuf + HDIM);
    logits_cvt<<<NLOGBLK, 512>>>(Wout, wout16, bout, h1 + HDIM, gl, gp);

    // ---- steps 1..A-1: R11 steady state ----
    for (int s = 1; s < ANUM; s++) {
        const int r = s & 1;
        const int w = 1 - r;
        float* h0_in  = h0 + (size_t)r * HDIM;
        float* h0_out = h0 + (size_t)w * HDIM;
        float* h1_in  = h1 + (size_t)r * HDIM;
        float* h1_out = h1 + (size_t)w * HDIM;

        step_k1<0><<<NB_A + NB_B, 512, SM_K1>>>(
            wih16, whh16, whh16 + wOffL,
            bih, bhh, bih + bOffL, bhh + bOffL,
            nullptr, gl, gp, out + (size_t)(s - 1) * SDIM,
            h0_in, h0_out, h1_in, cbuf, pre1);
        step_k2<<<NB_A, 512, SM_K2>>>(
            wih16 + wOffL, pre1, h0_out, h1_out, cbuf + HDIM);
        step_k3<<<NB_3, 512, SM_K3>>>(
            wout16, bout, h1_out, gl, gp);
    }

    final_softmax_kernel<<<1, 512>>>(gl, gp, out + (size_t)(ANUM - 1) * SDIM);
}